// round 15
// baseline (speedup 1.0000x reference)
#include <cuda_runtime.h>
#include <cuda_fp16.h>
#include <cstdint>

#define B_  32
#define N_  4096
#define CI_ 128
#define CO_ 128
#define M_  256
#define KSPLIT 9
#define KSEG0  448   // 7 x 64; last split gets 512 = 8 x 64

// ---------------- device scratch (no allocations allowed) ----------------
__device__ float g_xspec[B_ * M_ * CI_];                    // accumulated x_spec 4 MB
__device__ __half g_Wt16[M_ * CI_ * CO_];                   // [m][c][o] fp16 8 MB
__device__ __half g_U16[N_ * M_];                           // U fp16 [n][m] 2 MB
__device__ __half g_oM16[B_ * M_ * CO_];                    // mixed spec fp16 [b][m][o] 2 MB

// ---------------- helpers ----------------
__device__ __forceinline__ uint32_t s2u(const void* p) {
    uint32_t a;
    asm("{ .reg .u64 t; cvta.to.shared.u64 t, %1; cvt.u32.u64 %0, t; }" : "=r"(a) : "l"(p));
    return a;
}
#define SW128(o) ((o) ^ (((o) >> 3) & 0x70))

#define LDSM4(d0, d1, d2, d3, addr)                                                  \
    asm volatile("ldmatrix.sync.aligned.m8n8.x4.shared.b16 {%0,%1,%2,%3}, [%4];"     \
                 : "=r"(d0), "=r"(d1), "=r"(d2), "=r"(d3) : "r"(addr))

#define LDSM4T(d0, d1, d2, d3, addr)                                                 \
    asm volatile("ldmatrix.sync.aligned.m8n8.x4.trans.shared.b16 {%0,%1,%2,%3}, [%4];" \
                 : "=r"(d0), "=r"(d1), "=r"(d2), "=r"(d3) : "r"(addr))

#define MMA16816(d0, d1, d2, d3, a0, a1, a2, a3, b0, b1)                             \
    asm volatile("mma.sync.aligned.m16n8k16.row.col.f32.f16.f16.f32 "                \
                 "{%0,%1,%2,%3},{%4,%5,%6,%7},{%8,%9},{%0,%1,%2,%3};"                \
                 : "+f"(d0), "+f"(d1), "+f"(d2), "+f"(d3)                            \
                 : "r"(a0), "r"(a1), "r"(a2), "r"(a3), "r"(b0), "r"(b1))

#define CP_ASYNC16(saddr, gptr) \
    asm volatile("cp.async.cg.shared.global [%0], [%1], 16;" :: "r"(saddr), "l"(gptr))
#define CP_COMMIT() asm volatile("cp.async.commit_group;" ::: "memory")
#define CP_WAIT1()  asm volatile("cp.async.wait_group 1;" ::: "memory")

#define REDGF(ptr, val) \
    asm volatile("red.global.add.f32 [%0], %1;" :: "l"(ptr), "f"(val) : "memory")

// trans-fragment address inside a [64k x 128col] fp16 tile with seg^k swizzle.
#define TADDR(tile, ks, col0) \
    ((tile) + (ks) * 4096 + kboff + (((((col0) >> 3) + cadd) ^ l7) << 4))

// load 4 n-block B fragments (32 cols) of chunk ks from a trans tile (single buf)
#define LOADB_T(dst, bTile, ks) do {                                                 \
    uint32_t _r0, _r1, _r2, _r3;                                                     \
    LDSM4T(_r0, _r1, _r2, _r3, TADDR(bTile, ks, wn * 32));                           \
    dst[0][0] = _r0; dst[1][0] = _r1; dst[0][1] = _r2; dst[1][1] = _r3;              \
    LDSM4T(_r0, _r1, _r2, _r3, TADDR(bTile, ks, wn * 32 + 16));                      \
    dst[2][0] = _r0; dst[3][0] = _r1; dst[2][1] = _r2; dst[3][1] = _r3;              \
} while (0)

// B-chunk gmem load (fp32) and cvt+STS (fp16 trans layout)
#define LDGB(q, Bx, kkk, ii) do {                                                    \
    int _idx = tid + (ii) * 256;                                                     \
    int _k = _idx >> 4, _seg = _idx & 15;                                            \
    const float4* _s = (const float4*)((Bx) + (size_t)((kkk) + _k) * CI_ + _seg * 8);\
    q[0] = _s[0]; q[1] = _s[1];                                                      \
} while (0)

#define STSB(q, off, ii) do {                                                        \
    int _idx = tid + (ii) * 256;                                                     \
    int _k = _idx >> 4, _seg = _idx & 15;                                            \
    uint32_t _sa = smb + (off) + 16384 + _k * 256 + ((_seg ^ (_k & 7)) << 4);        \
    union { __half2 h[4]; uint4 u; } _cv;                                            \
    _cv.h[0] = __floats2half2_rn(q[0].x, q[0].y);                                    \
    _cv.h[1] = __floats2half2_rn(q[0].z, q[0].w);                                    \
    _cv.h[2] = __floats2half2_rn(q[1].x, q[1].y);                                    \
    _cv.h[3] = __floats2half2_rn(q[1].z, q[1].w);                                    \
    asm volatile("st.shared.v4.b32 [%0], {%1,%2,%3,%4};"                             \
                 :: "r"(_sa), "r"(_cv.u.x), "r"(_cv.u.y), "r"(_cv.u.z), "r"(_cv.u.w) \
                 : "memory");                                                        \
} while (0)

// packed f32x2 (for kMix)
__device__ __forceinline__ unsigned long long pk2(float lo, float hi) {
    unsigned long long r;
    asm("mov.b64 %0, {%1, %2};" : "=l"(r) : "f"(lo), "f"(hi));
    return r;
}
__device__ __forceinline__ unsigned long long ffma2(unsigned long long a,
                                                    unsigned long long b,
                                                    unsigned long long c) {
    unsigned long long d;
    asm("fma.rn.f32x2 %0, %1, %2, %3;" : "=l"(d) : "l"(a), "l"(b), "l"(c));
    return d;
}
__device__ __forceinline__ void upk2(unsigned long long v, float& lo, float& hi) {
    asm("mov.b64 {%0, %1}, %2;" : "=f"(lo), "=f"(hi) : "l"(v));
}

// ---------------- fused prep kernel (U cast + W transpose/cast + zero) -------
#define PB_U 256
#define PB_W (PB_U + 4096)
#define PREP_TOTAL (PB_W + 256)

__global__ void __launch_bounds__(256) kPrep(const float* __restrict__ U,
                                             const float* __restrict__ W) {
    int tid = threadIdx.x;
    int bid = blockIdx.x;
    if (bid < PB_U) {
        const float4* src = (const float4*)U;
        size_t base = (size_t)bid * 1024 + tid;
#pragma unroll
        for (int i = 0; i < 4; i++) {
            size_t c = base + i * 256;
            float4 v = src[c];
            union { __half2 h[2]; uint2 u; } cv;
            cv.h[0] = __floats2half2_rn(v.x, v.y);
            cv.h[1] = __floats2half2_rn(v.z, v.w);
            ((uint2*)g_U16)[c] = cv.u;
        }
    } else if (bid < PB_W) {
        __shared__ float tile[32][33];
        int t = bid - PB_U;
        int tx = tid & 31, ty = tid >> 5;
        int m0 = (t & 7) * 32, o0 = ((t >> 3) & 3) * 32, c = t >> 5;
        const float* Wc = W + (size_t)c * CO_ * M_;
#pragma unroll
        for (int j = 0; j < 4; j++)
            tile[ty + j * 8][tx] = Wc[(size_t)(o0 + ty + j * 8) * M_ + m0 + tx];
        __syncthreads();
#pragma unroll
        for (int j = 0; j < 4; j++)
            g_Wt16[(size_t)(m0 + ty + j * 8) * CI_ * CO_ + (size_t)c * CO_ + o0 + tx] =
                __float2half(tile[tx][ty + j * 8]);
    } else {
        int t = bid - PB_W;
        float4* p = (float4*)g_xspec + (size_t)t * 1024;
#pragma unroll
        for (int i = 0; i < 4; i++)
            p[tid + i * 256] = make_float4(0.f, 0.f, 0.f, 0.f);
    }
}

#define STG_BYTES 32768
#define SM_TOTAL  (3 * STG_BYTES)

// ---------------- GEMM1 with fused x cast (unchanged from R14) ----------------
__global__ void __launch_bounds__(256, 2) kGemm1F(
    const __half* __restrict__ U16p, const float* __restrict__ x32,
    float* __restrict__ C)
{
    extern __shared__ char sm[];
    const uint32_t smb = s2u(sm);
    const int tid = threadIdx.x, lane = tid & 31, wid = tid >> 5;
    const int wm = wid >> 2, wn = wid & 3;
    const int row0 = blockIdx.x * 128, b = blockIdx.y, kz = blockIdx.z;
    const int kbase = kz * KSEG0;
    const int Kseg = (kz == KSPLIT - 1) ? (N_ - kbase) : KSEG0;
    const int S = Kseg / 64;

    const float* Bx = x32 + (size_t)b * N_ * CI_;
    float* Cb = C + (size_t)b * M_ * CI_ + (size_t)row0 * 128;

    const int l7 = lane & 7;
    const int cadd = (lane >> 3) & 1;
    const uint32_t kboff = (uint32_t)((((lane & 16) >> 1) + l7) * 256);

    float acc[4][4][4];
#pragma unroll
    for (int i = 0; i < 4; i++)
#pragma unroll
        for (int j = 0; j < 4; j++)
#pragma unroll
            for (int q = 0; q < 4; q++) acc[i][j][q] = 0.f;

    auto issueA = [&](int off, int kk) {
#pragma unroll
        for (int i = 0; i < 4; i++) {
            int idx = tid + i * 256;
            int k = idx >> 4, seg = idx & 15;
            CP_ASYNC16(smb + off + k * 256 + ((seg ^ (k & 7)) << 4),
                       U16p + (size_t)(kbase + kk + k) * M_ + row0 + seg * 8);
        }
    };

    issueA(0, 0);
    CP_COMMIT();
    if (S > 1) issueA(STG_BYTES, 64);
    CP_COMMIT();
    {
        float4 q[2];
#pragma unroll
        for (int i = 0; i < 4; i++) { LDGB(q, Bx, kbase, i); STSB(q, 0, i); }
    }

    float4 q0[2], q1[2];

    for (int s = 0; s < S; s++) {
        CP_WAIT1();
        __syncthreads();
        if (s + 2 < S) issueA(((s + 2) % 3) * STG_BYTES, (s + 2) * 64);
        CP_COMMIT();

        const int haveNext = (s + 1 < S);
        const int kk1 = kbase + (s + 1) * 64;
        const int nb = ((s + 1) % 3) * STG_BYTES;
        if (haveNext) { LDGB(q0, Bx, kk1, 0); LDGB(q1, Bx, kk1, 1); }

        const uint32_t stB = smb + (s % 3) * STG_BYTES;
        const uint32_t aT = stB, bT = stB + 16384;

        uint32_t bfr[4][2];
        uint32_t av[2][4];
#pragma unroll
        for (int ks = 0; ks < 4; ks++) {
            LOADB_T(bfr, bT, ks);
            LDSM4T(av[0][0], av[0][1], av[0][2], av[0][3],
                   TADDR(aT, ks, wm * 64));
#pragma unroll
            for (int mi = 0; mi < 4; mi++) {
                if (mi < 3)
                    LDSM4T(av[(mi + 1) & 1][0], av[(mi + 1) & 1][1],
                           av[(mi + 1) & 1][2], av[(mi + 1) & 1][3],
                           TADDR(aT, ks, wm * 64 + (mi + 1) * 16));
                uint32_t* a = av[mi & 1];
#pragma unroll
                for (int ni = 0; ni < 4; ni++)
                    MMA16816(acc[mi][ni][0], acc[mi][ni][1], acc[mi][ni][2], acc[mi][ni][3],
                             a[0], a[1], a[2], a[3],
                             bfr[ni][0], bfr[ni][1]);
            }
            if (ks == 0 && haveNext) { STSB(q0, nb, 0); LDGB(q0, Bx, kk1, 2); }
            if (ks == 1 && haveNext) { STSB(q1, nb, 1); LDGB(q1, Bx, kk1, 3); }
            if (ks == 2 && haveNext) { STSB(q0, nb, 2); }
            if (ks == 3 && haveNext) { STSB(q1, nb, 3); }
        }
    }

    int g = lane >> 2, tg = lane & 3;
#pragma unroll
    for (int mi = 0; mi < 4; mi++)
#pragma unroll
        for (int ni = 0; ni < 4; ni++) {
            int r = wm * 64 + mi * 16 + g;
            int col = wn * 32 + ni * 8 + tg * 2;
            float* p0 = &Cb[(size_t)r * 128 + col];
            float* p1 = &Cb[(size_t)(r + 8) * 128 + col];
            REDGF(p0, acc[mi][ni][0]);
            REDGF(p0 + 1, acc[mi][ni][1]);
            REDGF(p1, acc[mi][ni][2]);
            REDGF(p1 + 1, acc[mi][ni][3]);
        }
}

// ---------------- GEMM2: continuous 2-n-tile pipeline ------------------------
// out[b][n][o] = sum_m U[n][m] * oM[b][m][o]
// Each CTA sweeps 2 consecutive 128-row n-tiles as one 8-stage pipeline
// (stage = (tile, k-chunk)); tile-0 epilogue overlaps tile-1 loads.
__global__ void __launch_bounds__(256, 2) kGemm2(
    const __half* __restrict__ A16,
    const __half* __restrict__ B16,
    float* __restrict__ C)
{
    extern __shared__ char sm[];
    const uint32_t smb = s2u(sm);
    const int tid = threadIdx.x, lane = tid & 31, wid = tid >> 5;
    const int wm = wid >> 2, wn = wid & 3;
    const int nt0 = blockIdx.x * 2, b = blockIdx.y;

    const __half* Bb = B16 + (size_t)b * M_ * CO_;

    const int l7 = lane & 7;
    const int cadd = (lane >> 3) & 1;
    const uint32_t kboff = (uint32_t)((((lane & 16) >> 1) + l7) * 256);

    float acc[4][4][4];
#pragma unroll
    for (int i = 0; i < 4; i++)
#pragma unroll
        for (int j = 0; j < 4; j++)
#pragma unroll
            for (int q = 0; q < 4; q++) acc[i][j][q] = 0.f;

    auto issue = [&](int off, int st) {
        int row0 = (nt0 + (st >> 2)) * 128;
        int kk = (st & 3) * 64;
#pragma unroll
        for (int i = 0; i < 4; i++) {   // A plain tile
            int idx = tid + i * 256;
            int r = idx >> 3, ch = idx & 7;
            CP_ASYNC16(smb + off + SW128(r * 128 + ch * 16),
                       A16 + (size_t)(row0 + r) * M_ + kk + ch * 8);
        }
#pragma unroll
        for (int i = 0; i < 4; i++) {   // B trans tile
            int idx = tid + i * 256;
            int k = idx >> 4, seg = idx & 15;
            CP_ASYNC16(smb + off + 16384 + k * 256 + ((seg ^ (k & 7)) << 4),
                       Bb + (size_t)(kk + k) * CO_ + seg * 8);
        }
    };

    issue(0, 0);
    CP_COMMIT();
    issue(STG_BYTES, 1);
    CP_COMMIT();

    const int rA = wm * 64 + (lane & 15);
    const int g = lane >> 2, tg = lane & 3;

    for (int st = 0; st < 8; st++) {
        CP_WAIT1();
        __syncthreads();
        if (st + 2 < 8) issue(((st + 2) % 3) * STG_BYTES, st + 2);
        CP_COMMIT();

        const uint32_t stB = smb + (st % 3) * STG_BYTES;
        const uint32_t aT = stB, bT = stB + 16384;

        uint32_t bfr[2][4][2];
        uint32_t av[2][4];
        LOADB_T(bfr[0], bT, 0);
#pragma unroll
        for (int ks = 0; ks < 4; ks++) {
            const int kc16 = (ks * 2 + (lane >> 4)) * 16;
            if (ks < 3) LOADB_T(bfr[(ks + 1) & 1], bT, ks + 1);
            LDSM4(av[0][0], av[0][1], av[0][2], av[0][3],
                  aT + SW128(rA * 128 + kc16));
#pragma unroll
            for (int mi = 0; mi < 4; mi++) {
                if (mi < 3)
                    LDSM4(av[(mi + 1) & 1][0], av[(mi + 1) & 1][1],
                          av[(mi + 1) & 1][2], av[(mi + 1) & 1][3],
                          aT + SW128((rA + (mi + 1) * 16) * 128 + kc16));
                uint32_t* a = av[mi & 1];
#pragma unroll
                for (int ni = 0; ni < 4; ni++)
                    MMA16816(acc[mi][ni][0], acc[mi][ni][1], acc[mi][ni][2], acc[mi][ni][3],
                             a[0], a[1], a[2], a[3],
                             bfr[ks & 1][ni][0], bfr[ks & 1][ni][1]);
            }
        }

        if ((st & 3) == 3) {   // n-tile finished: write out, reset acc
            int row0 = (nt0 + (st >> 2)) * 128;
            float* Cb = C + (size_t)b * N_ * CO_ + (size_t)row0 * 128;
#pragma unroll
            for (int mi = 0; mi < 4; mi++)
#pragma unroll
                for (int ni = 0; ni < 4; ni++) {
                    int r = wm * 64 + mi * 16 + g;
                    int col = wn * 32 + ni * 8 + tg * 2;
                    *(float2*)&Cb[(size_t)r * 128 + col] =
                        make_float2(acc[mi][ni][0], acc[mi][ni][1]);
                    *(float2*)&Cb[(size_t)(r + 8) * 128 + col] =
                        make_float2(acc[mi][ni][2], acc[mi][ni][3]);
                    acc[mi][ni][0] = acc[mi][ni][1] = 0.f;
                    acc[mi][ni][2] = acc[mi][ni][3] = 0.f;
                }
        }
    }
}

// ---------------- per-mode channel mixing (single-sync, fp16 W) ---------------
__global__ void __launch_bounds__(256) kMix() {
    __shared__ float xs[32][128];
    __shared__ __half ws[128][64];
    int m = blockIdx.x, hh = blockIdx.y;
    int t = threadIdx.x;
#pragma unroll
    for (int i = 0; i < 4; i++) {
        int idx = i * 256 + t;
        int bb = idx >> 5;
        int cc = (idx & 31) << 2;
        *(float4*)&xs[bb][cc] =
            *(const float4*)&g_xspec[((size_t)bb * M_ + m) * CI_ + cc];
    }
    const __half* Wm = g_Wt16 + (size_t)m * CI_ * CO_ + hh * 64;
#pragma unroll
    for (int i = 0; i < 8; i++) {
        int idx = i * 256 + t;
        int cr = idx >> 4, oc = (idx & 15) << 2;
        *(uint2*)&ws[cr][oc] = *(const uint2*)&Wm[(size_t)cr * CO_ + oc];
    }
    __syncthreads();

    int tx = t & 15, ty = t >> 4;
    unsigned long long acc[2][2];
    acc[0][0] = acc[0][1] = acc[1][0] = acc[1][1] = 0ull;
#pragma unroll 16
    for (int k = 0; k < CI_; k++) {
        __half2 h01 = *(const __half2*)&ws[k][tx << 2];
        __half2 h23 = *(const __half2*)&ws[k][(tx << 2) + 2];
        float2 f01 = __half22float2(h01);
        float2 f23 = __half22float2(h23);
        unsigned long long b01 = pk2(f01.x, f01.y);
        unsigned long long b23 = pk2(f23.x, f23.y);
#pragma unroll
        for (int i = 0; i < 2; i++) {
            float a = xs[ty * 2 + i][k];
            unsigned long long ad = pk2(a, a);
            acc[i][0] = ffma2(ad, b01, acc[i][0]);
            acc[i][1] = ffma2(ad, b23, acc[i][1]);
        }
    }
#pragma unroll
    for (int i = 0; i < 2; i++) {
        float4 v;
        upk2(acc[i][0], v.x, v.y);
        upk2(acc[i][1], v.z, v.w);
        int bb = ty * 2 + i;
        union { __half2 h[2]; uint2 u; } cv;
        cv.h[0] = __floats2half2_rn(v.x, v.y);
        cv.h[1] = __floats2half2_rn(v.z, v.w);
        *(uint2*)(g_oM16 + ((size_t)bb * M_ + m) * CO_ + hh * 64 + (tx << 2)) = cv.u;
    }
}

// ---------------- launch ----------------
extern "C" void kernel_launch(void* const* d_in, const int* in_sizes, int n_in,
                              void* d_out, int out_size) {
    const float* x = (const float*)d_in[0];   // [B, N, C_in]
    const float* U = (const float*)d_in[1];   // [N, M]
    const float* W = (const float*)d_in[2];   // [C_in, C_out, M]
    float* out = (float*)d_out;               // [B, N, C_out]

    float* pXs;
    __half *pU, *pO;
    cudaGetSymbolAddress((void**)&pXs, g_xspec);
    cudaGetSymbolAddress((void**)&pU, g_U16);
    cudaGetSymbolAddress((void**)&pO, g_oM16);

    cudaFuncSetAttribute(kGemm1F, cudaFuncAttributeMaxDynamicSharedMemorySize, SM_TOTAL);
    cudaFuncSetAttribute(kGemm2, cudaFuncAttributeMaxDynamicSharedMemorySize, SM_TOTAL);

    // prep: U cast + W transpose/cast + zero g_xspec
    kPrep<<<PREP_TOTAL, 256>>>(U, W);

    // GEMM1 (fused x cast, REDG accumulate)
    kGemm1F<<<dim3(M_ / 128, B_, KSPLIT), 256, SM_TOTAL>>>(pU, x, pXs);

    // mixing
    kMix<<<dim3(M_, 2), 256>>>();

    // GEMM2: continuous 2-tile pipeline, grid (16, 32)
    kGemm2<<<dim3(N_ / 256, B_), 256, SM_TOTAL>>>(pU, pO, out);
}

// round 16
// speedup vs baseline: 1.0346x; 1.0346x over previous
#include <cuda_runtime.h>
#include <cuda_fp16.h>
#include <cstdint>

#define B_  32
#define N_  4096
#define CI_ 128
#define CO_ 128
#define M_  256
#define KSPLIT 9
#define KSEG0  448   // 7 x 64; last split gets 512 = 8 x 64

// ---------------- device scratch (no allocations allowed) ----------------
__device__ float g_xspec[B_ * M_ * CI_];                    // accumulated x_spec 4 MB
__device__ __half g_Wt16[M_ * CI_ * CO_];                   // [m][c][o] fp16 8 MB
__device__ __half g_U16[N_ * M_];                           // U fp16 [n][m] 2 MB
__device__ __half g_oM16[B_ * M_ * CO_];                    // mixed spec fp16 [b][m][o] 2 MB

// ---------------- helpers ----------------
__device__ __forceinline__ uint32_t s2u(const void* p) {
    uint32_t a;
    asm("{ .reg .u64 t; cvta.to.shared.u64 t, %1; cvt.u32.u64 %0, t; }" : "=r"(a) : "l"(p));
    return a;
}
#define SW128(o) ((o) ^ (((o) >> 3) & 0x70))

#define LDSM4(d0, d1, d2, d3, addr)                                                  \
    asm volatile("ldmatrix.sync.aligned.m8n8.x4.shared.b16 {%0,%1,%2,%3}, [%4];"     \
                 : "=r"(d0), "=r"(d1), "=r"(d2), "=r"(d3) : "r"(addr))

#define LDSM4T(d0, d1, d2, d3, addr)                                                 \
    asm volatile("ldmatrix.sync.aligned.m8n8.x4.trans.shared.b16 {%0,%1,%2,%3}, [%4];" \
                 : "=r"(d0), "=r"(d1), "=r"(d2), "=r"(d3) : "r"(addr))

#define MMA16816(d0, d1, d2, d3, a0, a1, a2, a3, b0, b1)                             \
    asm volatile("mma.sync.aligned.m16n8k16.row.col.f32.f16.f16.f32 "                \
                 "{%0,%1,%2,%3},{%4,%5,%6,%7},{%8,%9},{%0,%1,%2,%3};"                \
                 : "+f"(d0), "+f"(d1), "+f"(d2), "+f"(d3)                            \
                 : "r"(a0), "r"(a1), "r"(a2), "r"(a3), "r"(b0), "r"(b1))

#define CP_ASYNC16(saddr, gptr) \
    asm volatile("cp.async.cg.shared.global [%0], [%1], 16;" :: "r"(saddr), "l"(gptr))
#define CP_COMMIT() asm volatile("cp.async.commit_group;" ::: "memory")
#define CP_WAIT1()  asm volatile("cp.async.wait_group 1;" ::: "memory")
#define CP_WAIT0()  asm volatile("cp.async.wait_group 0;" ::: "memory")

#define REDGF(ptr, val) \
    asm volatile("red.global.add.f32 [%0], %1;" :: "l"(ptr), "f"(val) : "memory")

// trans-fragment address inside a [64k x 128col] fp16 tile with seg^k swizzle.
#define TADDR(tile, ks, col0) \
    ((tile) + (ks) * 4096 + kboff + (((((col0) >> 3) + cadd) ^ l7) << 4))

// load 4 n-block B fragments (32 cols) of chunk ks from a trans tile (single buf)
#define LOADB_T(dst, bTile, ks) do {                                                 \
    uint32_t _r0, _r1, _r2, _r3;                                                     \
    LDSM4T(_r0, _r1, _r2, _r3, TADDR(bTile, ks, wn * 32));                           \
    dst[0][0] = _r0; dst[1][0] = _r1; dst[0][1] = _r2; dst[1][1] = _r3;              \
    LDSM4T(_r0, _r1, _r2, _r3, TADDR(bTile, ks, wn * 32 + 16));                      \
    dst[2][0] = _r0; dst[3][0] = _r1; dst[2][1] = _r2; dst[3][1] = _r3;              \
} while (0)

// B-chunk gmem load (fp32) and cvt+STS (fp16 trans layout)
#define LDGB(q, Bx, kkk, ii) do {                                                    \
    int _idx = tid + (ii) * 256;                                                     \
    int _k = _idx >> 4, _seg = _idx & 15;                                            \
    const float4* _s = (const float4*)((Bx) + (size_t)((kkk) + _k) * CI_ + _seg * 8);\
    q[0] = _s[0]; q[1] = _s[1];                                                      \
} while (0)

#define STSB(q, off, ii) do {                                                        \
    int _idx = tid + (ii) * 256;                                                     \
    int _k = _idx >> 4, _seg = _idx & 15;                                            \
    uint32_t _sa = smb + (off) + 16384 + _k * 256 + ((_seg ^ (_k & 7)) << 4);        \
    union { __half2 h[4]; uint4 u; } _cv;                                            \
    _cv.h[0] = __floats2half2_rn(q[0].x, q[0].y);                                    \
    _cv.h[1] = __floats2half2_rn(q[0].z, q[0].w);                                    \
    _cv.h[2] = __floats2half2_rn(q[1].x, q[1].y);                                    \
    _cv.h[3] = __floats2half2_rn(q[1].z, q[1].w);                                    \
    asm volatile("st.shared.v4.b32 [%0], {%1,%2,%3,%4};"                             \
                 :: "r"(_sa), "r"(_cv.u.x), "r"(_cv.u.y), "r"(_cv.u.z), "r"(_cv.u.w) \
                 : "memory");                                                        \
} while (0)

// packed f32x2 (for kMix)
__device__ __forceinline__ unsigned long long pk2(float lo, float hi) {
    unsigned long long r;
    asm("mov.b64 %0, {%1, %2};" : "=l"(r) : "f"(lo), "f"(hi));
    return r;
}
__device__ __forceinline__ unsigned long long ffma2(unsigned long long a,
                                                    unsigned long long b,
                                                    unsigned long long c) {
    unsigned long long d;
    asm("fma.rn.f32x2 %0, %1, %2, %3;" : "=l"(d) : "l"(a), "l"(b), "l"(c));
    return d;
}
__device__ __forceinline__ void upk2(unsigned long long v, float& lo, float& hi) {
    asm("mov.b64 {%0, %1}, %2;" : "=f"(lo), "=f"(hi) : "l"(v));
}

// ---------------- fused prep kernel (U cast + W transpose/cast + zero) -------
#define PB_U 256
#define PB_W (PB_U + 4096)
#define PREP_TOTAL (PB_W + 256)

__global__ void __launch_bounds__(256) kPrep(const float* __restrict__ U,
                                             const float* __restrict__ W) {
    int tid = threadIdx.x;
    int bid = blockIdx.x;
    if (bid < PB_U) {
        const float4* src = (const float4*)U;
        size_t base = (size_t)bid * 1024 + tid;
#pragma unroll
        for (int i = 0; i < 4; i++) {
            size_t c = base + i * 256;
            float4 v = src[c];
            union { __half2 h[2]; uint2 u; } cv;
            cv.h[0] = __floats2half2_rn(v.x, v.y);
            cv.h[1] = __floats2half2_rn(v.z, v.w);
            ((uint2*)g_U16)[c] = cv.u;
        }
    } else if (bid < PB_W) {
        __shared__ float tile[32][33];
        int t = bid - PB_U;
        int tx = tid & 31, ty = tid >> 5;
        int m0 = (t & 7) * 32, o0 = ((t >> 3) & 3) * 32, c = t >> 5;
        const float* Wc = W + (size_t)c * CO_ * M_;
#pragma unroll
        for (int j = 0; j < 4; j++)
            tile[ty + j * 8][tx] = Wc[(size_t)(o0 + ty + j * 8) * M_ + m0 + tx];
        __syncthreads();
#pragma unroll
        for (int j = 0; j < 4; j++)
            g_Wt16[(size_t)(m0 + ty + j * 8) * CI_ * CO_ + (size_t)c * CO_ + o0 + tx] =
                __float2half(tile[tx][ty + j * 8]);
    } else {
        int t = bid - PB_W;
        float4* p = (float4*)g_xspec + (size_t)t * 1024;
#pragma unroll
        for (int i = 0; i < 4; i++)
            p[tid + i * 256] = make_float4(0.f, 0.f, 0.f, 0.f);
    }
}

#define STG_BYTES 32768
#define SM_TOTAL  (3 * STG_BYTES)

// ---------------- GEMM1 with fused x cast (unchanged from R14) ----------------
__global__ void __launch_bounds__(256, 2) kGemm1F(
    const __half* __restrict__ U16p, const float* __restrict__ x32,
    float* __restrict__ C)
{
    extern __shared__ char sm[];
    const uint32_t smb = s2u(sm);
    const int tid = threadIdx.x, lane = tid & 31, wid = tid >> 5;
    const int wm = wid >> 2, wn = wid & 3;
    const int row0 = blockIdx.x * 128, b = blockIdx.y, kz = blockIdx.z;
    const int kbase = kz * KSEG0;
    const int Kseg = (kz == KSPLIT - 1) ? (N_ - kbase) : KSEG0;
    const int S = Kseg / 64;

    const float* Bx = x32 + (size_t)b * N_ * CI_;
    float* Cb = C + (size_t)b * M_ * CI_ + (size_t)row0 * 128;

    const int l7 = lane & 7;
    const int cadd = (lane >> 3) & 1;
    const uint32_t kboff = (uint32_t)((((lane & 16) >> 1) + l7) * 256);

    float acc[4][4][4];
#pragma unroll
    for (int i = 0; i < 4; i++)
#pragma unroll
        for (int j = 0; j < 4; j++)
#pragma unroll
            for (int q = 0; q < 4; q++) acc[i][j][q] = 0.f;

    auto issueA = [&](int off, int kk) {
#pragma unroll
        for (int i = 0; i < 4; i++) {
            int idx = tid + i * 256;
            int k = idx >> 4, seg = idx & 15;
            CP_ASYNC16(smb + off + k * 256 + ((seg ^ (k & 7)) << 4),
                       U16p + (size_t)(kbase + kk + k) * M_ + row0 + seg * 8);
        }
    };

    issueA(0, 0);
    CP_COMMIT();
    if (S > 1) issueA(STG_BYTES, 64);
    CP_COMMIT();
    {
        float4 q[2];
#pragma unroll
        for (int i = 0; i < 4; i++) { LDGB(q, Bx, kbase, i); STSB(q, 0, i); }
    }

    float4 q0[2], q1[2];

    for (int s = 0; s < S; s++) {
        CP_WAIT1();
        __syncthreads();
        if (s + 2 < S) issueA(((s + 2) % 3) * STG_BYTES, (s + 2) * 64);
        CP_COMMIT();

        const int haveNext = (s + 1 < S);
        const int kk1 = kbase + (s + 1) * 64;
        const int nb = ((s + 1) % 3) * STG_BYTES;
        if (haveNext) { LDGB(q0, Bx, kk1, 0); LDGB(q1, Bx, kk1, 1); }

        const uint32_t stB = smb + (s % 3) * STG_BYTES;
        const uint32_t aT = stB, bT = stB + 16384;

        uint32_t bfr[4][2];
        uint32_t av[2][4];
#pragma unroll
        for (int ks = 0; ks < 4; ks++) {
            LOADB_T(bfr, bT, ks);
            LDSM4T(av[0][0], av[0][1], av[0][2], av[0][3],
                   TADDR(aT, ks, wm * 64));
#pragma unroll
            for (int mi = 0; mi < 4; mi++) {
                if (mi < 3)
                    LDSM4T(av[(mi + 1) & 1][0], av[(mi + 1) & 1][1],
                           av[(mi + 1) & 1][2], av[(mi + 1) & 1][3],
                           TADDR(aT, ks, wm * 64 + (mi + 1) * 16));
                uint32_t* a = av[mi & 1];
#pragma unroll
                for (int ni = 0; ni < 4; ni++)
                    MMA16816(acc[mi][ni][0], acc[mi][ni][1], acc[mi][ni][2], acc[mi][ni][3],
                             a[0], a[1], a[2], a[3],
                             bfr[ni][0], bfr[ni][1]);
            }
            if (ks == 0 && haveNext) { STSB(q0, nb, 0); LDGB(q0, Bx, kk1, 2); }
            if (ks == 1 && haveNext) { STSB(q1, nb, 1); LDGB(q1, Bx, kk1, 3); }
            if (ks == 2 && haveNext) { STSB(q0, nb, 2); }
            if (ks == 3 && haveNext) { STSB(q1, nb, 3); }
        }
    }

    int g = lane >> 2, tg = lane & 3;
#pragma unroll
    for (int mi = 0; mi < 4; mi++)
#pragma unroll
        for (int ni = 0; ni < 4; ni++) {
            int r = wm * 64 + mi * 16 + g;
            int col = wn * 32 + ni * 8 + tg * 2;
            float* p0 = &Cb[(size_t)r * 128 + col];
            float* p1 = &Cb[(size_t)(r + 8) * 128 + col];
            REDGF(p0, acc[mi][ni][0]);
            REDGF(p0 + 1, acc[mi][ni][1]);
            REDGF(p1, acc[mi][ni][2]);
            REDGF(p1 + 1, acc[mi][ni][3]);
        }
}

// ---------------- GEMM2: 128-thread CTA, 64x128 tile, 2-stage, 4 CTAs/SM -----
// out[b][n][o] = sum_m U[n][m] * oM[b][m][o]
#define G2_STG 24576            // A 8K + B 16K
#define G2_SM  (2 * G2_STG)     // 48 KB

__global__ void __launch_bounds__(128, 4) kGemm2(
    const __half* __restrict__ A16,
    const __half* __restrict__ B16,
    float* __restrict__ C)
{
    extern __shared__ char sm[];
    const uint32_t smb = s2u(sm);
    const int tid = threadIdx.x, lane = tid & 31, wn = tid >> 5;  // 4 warps
    const int row0 = blockIdx.x * 64, b = blockIdx.y;

    const __half* Bb = B16 + (size_t)b * M_ * CO_;
    float* Cb = C + (size_t)b * N_ * CO_ + (size_t)row0 * 128;

    const int l7 = lane & 7;
    const int cadd = (lane >> 3) & 1;
    const uint32_t kboff = (uint32_t)((((lane & 16) >> 1) + l7) * 256);

    float acc[4][4][4];
#pragma unroll
    for (int i = 0; i < 4; i++)
#pragma unroll
        for (int j = 0; j < 4; j++)
#pragma unroll
            for (int q = 0; q < 4; q++) acc[i][j][q] = 0.f;

    auto issue = [&](int off, int s) {
        int kk = s * 64;
#pragma unroll
        for (int i = 0; i < 4; i++) {   // A plain: 64 rows x 8 chunks = 512
            int idx = tid + i * 128;
            int r = idx >> 3, ch = idx & 7;
            CP_ASYNC16(smb + off + SW128(r * 128 + ch * 16),
                       A16 + (size_t)(row0 + r) * M_ + kk + ch * 8);
        }
#pragma unroll
        for (int i = 0; i < 8; i++) {   // B trans: 64 k x 16 segs = 1024
            int idx = tid + i * 128;
            int k = idx >> 4, seg = idx & 15;
            CP_ASYNC16(smb + off + 8192 + k * 256 + ((seg ^ (k & 7)) << 4),
                       Bb + (size_t)(kk + k) * CO_ + seg * 8);
        }
    };

    issue(0, 0);
    CP_COMMIT();

    const int rA = lane & 15;   // row within 64 (wm = 0)
    const int g = lane >> 2, tg = lane & 3;

    for (int s = 0; s < 4; s++) {
        CP_WAIT0();
        __syncthreads();
        if (s + 1 < 4) { issue(((s + 1) & 1) * G2_STG, s + 1); CP_COMMIT(); }

        const uint32_t stB = smb + (s & 1) * G2_STG;
        const uint32_t aT = stB, bT = stB + 8192;

        uint32_t bfr[2][4][2];
        uint32_t av[2][4];
        LOADB_T(bfr[0], bT, 0);
#pragma unroll
        for (int ks = 0; ks < 4; ks++) {
            const int kc16 = (ks * 2 + (lane >> 4)) * 16;
            if (ks < 3) LOADB_T(bfr[(ks + 1) & 1], bT, ks + 1);
            LDSM4(av[0][0], av[0][1], av[0][2], av[0][3],
                  aT + SW128(rA * 128 + kc16));
#pragma unroll
            for (int mi = 0; mi < 4; mi++) {
                if (mi < 3)
                    LDSM4(av[(mi + 1) & 1][0], av[(mi + 1) & 1][1],
                          av[(mi + 1) & 1][2], av[(mi + 1) & 1][3],
                          aT + SW128((rA + (mi + 1) * 16) * 128 + kc16));
                uint32_t* a = av[mi & 1];
#pragma unroll
                for (int ni = 0; ni < 4; ni++)
                    MMA16816(acc[mi][ni][0], acc[mi][ni][1], acc[mi][ni][2], acc[mi][ni][3],
                             a[0], a[1], a[2], a[3],
                             bfr[ks & 1][ni][0], bfr[ks & 1][ni][1]);
            }
        }
    }

#pragma unroll
    for (int mi = 0; mi < 4; mi++)
#pragma unroll
        for (int ni = 0; ni < 4; ni++) {
            int r = mi * 16 + g;
            int col = wn * 32 + ni * 8 + tg * 2;
            *(float2*)&Cb[(size_t)r * 128 + col] =
                make_float2(acc[mi][ni][0], acc[mi][ni][1]);
            *(float2*)&Cb[(size_t)(r + 8) * 128 + col] =
                make_float2(acc[mi][ni][2], acc[mi][ni][3]);
        }
}

// ---------------- per-mode channel mixing (single-sync, fp16 W) ---------------
__global__ void __launch_bounds__(256) kMix() {
    __shared__ float xs[32][128];
    __shared__ __half ws[128][64];
    int m = blockIdx.x, hh = blockIdx.y;
    int t = threadIdx.x;
#pragma unroll
    for (int i = 0; i < 4; i++) {
        int idx = i * 256 + t;
        int bb = idx >> 5;
        int cc = (idx & 31) << 2;
        *(float4*)&xs[bb][cc] =
            *(const float4*)&g_xspec[((size_t)bb * M_ + m) * CI_ + cc];
    }
    const __half* Wm = g_Wt16 + (size_t)m * CI_ * CO_ + hh * 64;
#pragma unroll
    for (int i = 0; i < 8; i++) {
        int idx = i * 256 + t;
        int cr = idx >> 4, oc = (idx & 15) << 2;
        *(uint2*)&ws[cr][oc] = *(const uint2*)&Wm[(size_t)cr * CO_ + oc];
    }
    __syncthreads();

    int tx = t & 15, ty = t >> 4;
    unsigned long long acc[2][2];
    acc[0][0] = acc[0][1] = acc[1][0] = acc[1][1] = 0ull;
#pragma unroll 16
    for (int k = 0; k < CI_; k++) {
        __half2 h01 = *(const __half2*)&ws[k][tx << 2];
        __half2 h23 = *(const __half2*)&ws[k][(tx << 2) + 2];
        float2 f01 = __half22float2(h01);
        float2 f23 = __half22float2(h23);
        unsigned long long b01 = pk2(f01.x, f01.y);
        unsigned long long b23 = pk2(f23.x, f23.y);
#pragma unroll
        for (int i = 0; i < 2; i++) {
            float a = xs[ty * 2 + i][k];
            unsigned long long ad = pk2(a, a);
            acc[i][0] = ffma2(ad, b01, acc[i][0]);
            acc[i][1] = ffma2(ad, b23, acc[i][1]);
        }
    }
#pragma unroll
    for (int i = 0; i < 2; i++) {
        float4 v;
        upk2(acc[i][0], v.x, v.y);
        upk2(acc[i][1], v.z, v.w);
        int bb = ty * 2 + i;
        union { __half2 h[2]; uint2 u; } cv;
        cv.h[0] = __floats2half2_rn(v.x, v.y);
        cv.h[1] = __floats2half2_rn(v.z, v.w);
        *(uint2*)(g_oM16 + ((size_t)bb * M_ + m) * CO_ + hh * 64 + (tx << 2)) = cv.u;
    }
}

// ---------------- launch ----------------
extern "C" void kernel_launch(void* const* d_in, const int* in_sizes, int n_in,
                              void* d_out, int out_size) {
    const float* x = (const float*)d_in[0];   // [B, N, C_in]
    const float* U = (const float*)d_in[1];   // [N, M]
    const float* W = (const float*)d_in[2];   // [C_in, C_out, M]
    float* out = (float*)d_out;               // [B, N, C_out]

    float* pXs;
    __half *pU, *pO;
    cudaGetSymbolAddress((void**)&pXs, g_xspec);
    cudaGetSymbolAddress((void**)&pU, g_U16);
    cudaGetSymbolAddress((void**)&pO, g_oM16);

    cudaFuncSetAttribute(kGemm1F, cudaFuncAttributeMaxDynamicSharedMemorySize, SM_TOTAL);
    cudaFuncSetAttribute(kGemm2, cudaFuncAttributeMaxDynamicSharedMemorySize, G2_SM);

    // prep: U cast + W transpose/cast + zero g_xspec
    kPrep<<<PREP_TOTAL, 256>>>(U, W);

    // GEMM1 (fused x cast, REDG accumulate)
    kGemm1F<<<dim3(M_ / 128, B_, KSPLIT), 256, SM_TOTAL>>>(pU, x, pXs);

    // mixing
    kMix<<<dim3(M_, 2), 256>>>();

    // GEMM2: 64-row tiles, 4 CTAs/SM, grid (64, 32)
    kGemm2<<<dim3(N_ / 64, B_), 128, G2_SM>>>(pU, pO, out);
}

// round 17
// speedup vs baseline: 1.0413x; 1.0065x over previous
#include <cuda_runtime.h>
#include <cuda_fp16.h>
#include <cstdint>

#define B_  32
#define N_  4096
#define CI_ 128
#define CO_ 128
#define M_  256
#define KSPLIT 9
#define KSEG0  448   // 7 x 64; last split gets 512 = 8 x 64

// ---------------- device scratch (no allocations allowed) ----------------
__device__ float g_xspec[B_ * M_ * CI_];                    // accumulated x_spec 4 MB
__device__ __half g_Wt16[M_ * CI_ * CO_];                   // [m][c][o] fp16 8 MB
__device__ __half g_U16[N_ * M_];                           // U fp16 [n][m] 2 MB
__device__ __half g_oM16[B_ * M_ * CO_];                    // mixed spec fp16 [b][m][o] 2 MB

// ---------------- helpers ----------------
__device__ __forceinline__ uint32_t s2u(const void* p) {
    uint32_t a;
    asm("{ .reg .u64 t; cvta.to.shared.u64 t, %1; cvt.u32.u64 %0, t; }" : "=r"(a) : "l"(p));
    return a;
}
#define SW128(o) ((o) ^ (((o) >> 3) & 0x70))

#define LDSM4(d0, d1, d2, d3, addr)                                                  \
    asm volatile("ldmatrix.sync.aligned.m8n8.x4.shared.b16 {%0,%1,%2,%3}, [%4];"     \
                 : "=r"(d0), "=r"(d1), "=r"(d2), "=r"(d3) : "r"(addr))

#define LDSM4T(d0, d1, d2, d3, addr)                                                 \
    asm volatile("ldmatrix.sync.aligned.m8n8.x4.trans.shared.b16 {%0,%1,%2,%3}, [%4];" \
                 : "=r"(d0), "=r"(d1), "=r"(d2), "=r"(d3) : "r"(addr))

#define MMA16816(d0, d1, d2, d3, a0, a1, a2, a3, b0, b1)                             \
    asm volatile("mma.sync.aligned.m16n8k16.row.col.f32.f16.f16.f32 "                \
                 "{%0,%1,%2,%3},{%4,%5,%6,%7},{%8,%9},{%0,%1,%2,%3};"                \
                 : "+f"(d0), "+f"(d1), "+f"(d2), "+f"(d3)                            \
                 : "r"(a0), "r"(a1), "r"(a2), "r"(a3), "r"(b0), "r"(b1))

#define CP_ASYNC16(saddr, gptr) \
    asm volatile("cp.async.cg.shared.global [%0], [%1], 16;" :: "r"(saddr), "l"(gptr))
#define CP_COMMIT() asm volatile("cp.async.commit_group;" ::: "memory")
#define CP_WAIT1()  asm volatile("cp.async.wait_group 1;" ::: "memory")
#define CP_WAIT0()  asm volatile("cp.async.wait_group 0;" ::: "memory")

#define REDGF(ptr, val) \
    asm volatile("red.global.add.f32 [%0], %1;" :: "l"(ptr), "f"(val) : "memory")

// trans-fragment address inside a [64k x 128col] fp16 tile with seg^k swizzle.
#define TADDR(tile, ks, col0) \
    ((tile) + (ks) * 4096 + kboff + (((((col0) >> 3) + cadd) ^ l7) << 4))

// load 4 n-block B fragments (32 cols) of chunk ks from a trans tile
#define LOADB_T(dst, bTile, ks) do {                                                 \
    uint32_t _r0, _r1, _r2, _r3;                                                     \
    LDSM4T(_r0, _r1, _r2, _r3, TADDR(bTile, ks, wn * 32));                           \
    dst[0][0] = _r0; dst[1][0] = _r1; dst[0][1] = _r2; dst[1][1] = _r3;              \
    LDSM4T(_r0, _r1, _r2, _r3, TADDR(bTile, ks, wn * 32 + 16));                      \
    dst[2][0] = _r0; dst[3][0] = _r1; dst[2][1] = _r2; dst[3][1] = _r3;              \
} while (0)

// B-chunk gmem load (fp32) and cvt+STS (fp16 trans layout) for GEMM1F
#define LDGB(q, Bx, kkk, ii) do {                                                    \
    int _idx = tid + (ii) * 256;                                                     \
    int _k = _idx >> 4, _seg = _idx & 15;                                            \
    const float4* _s = (const float4*)((Bx) + (size_t)((kkk) + _k) * CI_ + _seg * 8);\
    q[0] = _s[0]; q[1] = _s[1];                                                      \
} while (0)

#define STSB(q, off, ii) do {                                                        \
    int _idx = tid + (ii) * 256;                                                     \
    int _k = _idx >> 4, _seg = _idx & 15;                                            \
    uint32_t _sa = smb + (off) + 16384 + _k * 256 + ((_seg ^ (_k & 7)) << 4);        \
    union { __half2 h[4]; uint4 u; } _cv;                                            \
    _cv.h[0] = __floats2half2_rn(q[0].x, q[0].y);                                    \
    _cv.h[1] = __floats2half2_rn(q[0].z, q[0].w);                                    \
    _cv.h[2] = __floats2half2_rn(q[1].x, q[1].y);                                    \
    _cv.h[3] = __floats2half2_rn(q[1].z, q[1].w);                                    \
    asm volatile("st.shared.v4.b32 [%0], {%1,%2,%3,%4};"                             \
                 :: "r"(_sa), "r"(_cv.u.x), "r"(_cv.u.y), "r"(_cv.u.z), "r"(_cv.u.w) \
                 : "memory");                                                        \
} while (0)

// packed f32x2 (for kMix)
__device__ __forceinline__ unsigned long long pk2(float lo, float hi) {
    unsigned long long r;
    asm("mov.b64 %0, {%1, %2};" : "=l"(r) : "f"(lo), "f"(hi));
    return r;
}
__device__ __forceinline__ unsigned long long ffma2(unsigned long long a,
                                                    unsigned long long b,
                                                    unsigned long long c) {
    unsigned long long d;
    asm("fma.rn.f32x2 %0, %1, %2, %3;" : "=l"(d) : "l"(a), "l"(b), "l"(c));
    return d;
}
__device__ __forceinline__ void upk2(unsigned long long v, float& lo, float& hi) {
    asm("mov.b64 {%0, %1}, %2;" : "=f"(lo), "=f"(hi) : "l"(v));
}

// ---------------- fused prep kernel (U cast + W transpose/cast + zero) -------
#define PB_U 256
#define PB_W (PB_U + 4096)
#define PREP_TOTAL (PB_W + 256)

__global__ void __launch_bounds__(256) kPrep(const float* __restrict__ U,
                                             const float* __restrict__ W) {
    int tid = threadIdx.x;
    int bid = blockIdx.x;
    if (bid < PB_U) {
        const float4* src = (const float4*)U;
        size_t base = (size_t)bid * 1024 + tid;
#pragma unroll
        for (int i = 0; i < 4; i++) {
            size_t c = base + i * 256;
            float4 v = src[c];
            union { __half2 h[2]; uint2 u; } cv;
            cv.h[0] = __floats2half2_rn(v.x, v.y);
            cv.h[1] = __floats2half2_rn(v.z, v.w);
            ((uint2*)g_U16)[c] = cv.u;
        }
    } else if (bid < PB_W) {
        __shared__ float tile[32][33];
        int t = bid - PB_U;
        int tx = tid & 31, ty = tid >> 5;
        int m0 = (t & 7) * 32, o0 = ((t >> 3) & 3) * 32, c = t >> 5;
        const float* Wc = W + (size_t)c * CO_ * M_;
#pragma unroll
        for (int j = 0; j < 4; j++)
            tile[ty + j * 8][tx] = Wc[(size_t)(o0 + ty + j * 8) * M_ + m0 + tx];
        __syncthreads();
#pragma unroll
        for (int j = 0; j < 4; j++)
            g_Wt16[(size_t)(m0 + ty + j * 8) * CI_ * CO_ + (size_t)c * CO_ + o0 + tx] =
                __float2half(tile[tx][ty + j * 8]);
    } else {
        int t = bid - PB_W;
        float4* p = (float4*)g_xspec + (size_t)t * 1024;
#pragma unroll
        for (int i = 0; i < 4; i++)
            p[tid + i * 256] = make_float4(0.f, 0.f, 0.f, 0.f);
    }
}

#define STG_BYTES 32768
#define SM_TOTAL  (3 * STG_BYTES)

// ---------------- GEMM1 with fused x cast (unchanged from R14) ----------------
__global__ void __launch_bounds__(256, 2) kGemm1F(
    const __half* __restrict__ U16p, const float* __restrict__ x32,
    float* __restrict__ C)
{
    extern __shared__ char sm[];
    const uint32_t smb = s2u(sm);
    const int tid = threadIdx.x, lane = tid & 31, wid = tid >> 5;
    const int wm = wid >> 2, wn = wid & 3;
    const int row0 = blockIdx.x * 128, b = blockIdx.y, kz = blockIdx.z;
    const int kbase = kz * KSEG0;
    const int Kseg = (kz == KSPLIT - 1) ? (N_ - kbase) : KSEG0;
    const int S = Kseg / 64;

    const float* Bx = x32 + (size_t)b * N_ * CI_;
    float* Cb = C + (size_t)b * M_ * CI_ + (size_t)row0 * 128;

    const int l7 = lane & 7;
    const int cadd = (lane >> 3) & 1;
    const uint32_t kboff = (uint32_t)((((lane & 16) >> 1) + l7) * 256);

    float acc[4][4][4];
#pragma unroll
    for (int i = 0; i < 4; i++)
#pragma unroll
        for (int j = 0; j < 4; j++)
#pragma unroll
            for (int q = 0; q < 4; q++) acc[i][j][q] = 0.f;

    auto issueA = [&](int off, int kk) {
#pragma unroll
        for (int i = 0; i < 4; i++) {
            int idx = tid + i * 256;
            int k = idx >> 4, seg = idx & 15;
            CP_ASYNC16(smb + off + k * 256 + ((seg ^ (k & 7)) << 4),
                       U16p + (size_t)(kbase + kk + k) * M_ + row0 + seg * 8);
        }
    };

    issueA(0, 0);
    CP_COMMIT();
    if (S > 1) issueA(STG_BYTES, 64);
    CP_COMMIT();
    {
        float4 q[2];
#pragma unroll
        for (int i = 0; i < 4; i++) { LDGB(q, Bx, kbase, i); STSB(q, 0, i); }
    }

    float4 q0[2], q1[2];

    for (int s = 0; s < S; s++) {
        CP_WAIT1();
        __syncthreads();
        if (s + 2 < S) issueA(((s + 2) % 3) * STG_BYTES, (s + 2) * 64);
        CP_COMMIT();

        const int haveNext = (s + 1 < S);
        const int kk1 = kbase + (s + 1) * 64;
        const int nb = ((s + 1) % 3) * STG_BYTES;
        if (haveNext) { LDGB(q0, Bx, kk1, 0); LDGB(q1, Bx, kk1, 1); }

        const uint32_t stB = smb + (s % 3) * STG_BYTES;
        const uint32_t aT = stB, bT = stB + 16384;

        uint32_t bfr[4][2];
        uint32_t av[2][4];
#pragma unroll
        for (int ks = 0; ks < 4; ks++) {
            LOADB_T(bfr, bT, ks);
            LDSM4T(av[0][0], av[0][1], av[0][2], av[0][3],
                   TADDR(aT, ks, wm * 64));
#pragma unroll
            for (int mi = 0; mi < 4; mi++) {
                if (mi < 3)
                    LDSM4T(av[(mi + 1) & 1][0], av[(mi + 1) & 1][1],
                           av[(mi + 1) & 1][2], av[(mi + 1) & 1][3],
                           TADDR(aT, ks, wm * 64 + (mi + 1) * 16));
                uint32_t* a = av[mi & 1];
#pragma unroll
                for (int ni = 0; ni < 4; ni++)
                    MMA16816(acc[mi][ni][0], acc[mi][ni][1], acc[mi][ni][2], acc[mi][ni][3],
                             a[0], a[1], a[2], a[3],
                             bfr[ni][0], bfr[ni][1]);
            }
            if (ks == 0 && haveNext) { STSB(q0, nb, 0); LDGB(q0, Bx, kk1, 2); }
            if (ks == 1 && haveNext) { STSB(q1, nb, 1); LDGB(q1, Bx, kk1, 3); }
            if (ks == 2 && haveNext) { STSB(q0, nb, 2); }
            if (ks == 3 && haveNext) { STSB(q1, nb, 3); }
        }
    }

    int g = lane >> 2, tg = lane & 3;
#pragma unroll
    for (int mi = 0; mi < 4; mi++)
#pragma unroll
        for (int ni = 0; ni < 4; ni++) {
            int r = wm * 64 + mi * 16 + g;
            int col = wn * 32 + ni * 8 + tg * 2;
            float* p0 = &Cb[(size_t)r * 128 + col];
            float* p1 = &Cb[(size_t)(r + 8) * 128 + col];
            REDGF(p0, acc[mi][ni][0]);
            REDGF(p0 + 1, acc[mi][ni][1]);
            REDGF(p1, acc[mi][ni][2]);
            REDGF(p1 + 1, acc[mi][ni][3]);
        }
}

// ---------------- GEMM2: 64x128 tile, 4 CTAs/SM, full frag double-buffer -----
// out[b][n][o] = sum_m U[n][m] * oM[b][m][o]
#define G2_STG 24576            // A 8K + B 16K
#define G2_SM  (2 * G2_STG)     // 48 KB

__global__ void __launch_bounds__(128, 4) kGemm2(
    const __half* __restrict__ A16,
    const __half* __restrict__ B16,
    float* __restrict__ C)
{
    extern __shared__ char sm[];
    const uint32_t smb = s2u(sm);
    const int tid = threadIdx.x, lane = tid & 31, wn = tid >> 5;  // 4 warps
    const int row0 = blockIdx.x * 64, b = blockIdx.y;

    const __half* Bb = B16 + (size_t)b * M_ * CO_;
    float* Cb = C + (size_t)b * N_ * CO_ + (size_t)row0 * 128;

    const int l7 = lane & 7;
    const int cadd = (lane >> 3) & 1;
    const uint32_t kboff = (uint32_t)((((lane & 16) >> 1) + l7) * 256);

    float acc[4][4][4];
#pragma unroll
    for (int i = 0; i < 4; i++)
#pragma unroll
        for (int j = 0; j < 4; j++)
#pragma unroll
            for (int q = 0; q < 4; q++) acc[i][j][q] = 0.f;

    auto issue = [&](int off, int s) {
        int kk = s * 64;
#pragma unroll
        for (int i = 0; i < 4; i++) {   // A plain: 64 rows x 8 chunks = 512
            int idx = tid + i * 128;
            int r = idx >> 3, ch = idx & 7;
            CP_ASYNC16(smb + off + SW128(r * 128 + ch * 16),
                       A16 + (size_t)(row0 + r) * M_ + kk + ch * 8);
        }
#pragma unroll
        for (int i = 0; i < 8; i++) {   // B trans: 64 k x 16 segs = 1024
            int idx = tid + i * 128;
            int k = idx >> 4, seg = idx & 15;
            CP_ASYNC16(smb + off + 8192 + k * 256 + ((seg ^ (k & 7)) << 4),
                       Bb + (size_t)(kk + k) * CO_ + seg * 8);
        }
    };

    issue(0, 0);
    CP_COMMIT();

    const int rA = lane & 15;   // row within 64
    const int g = lane >> 2, tg = lane & 3;
    const int khi = (lane >> 4) * 16;   // k-half select for plain-A ldmatrix

    for (int s = 0; s < 4; s++) {
        CP_WAIT0();
        __syncthreads();
        if (s + 1 < 4) { issue(((s + 1) & 1) * G2_STG, s + 1); CP_COMMIT(); }

        const uint32_t stB = smb + (s & 1) * G2_STG;
        const uint32_t aT = stB, bT = stB + 8192;

        uint32_t bfr[2][4][2];
        uint32_t av[2][4][4];

        // preload chunk 0 fragments (2 B + 4 A ldmatrix)
        LOADB_T(bfr[0], bT, 0);
#pragma unroll
        for (int mi = 0; mi < 4; mi++)
            LDSM4(av[0][mi][0], av[0][mi][1], av[0][mi][2], av[0][mi][3],
                  aT + SW128((rA + mi * 16) * 128 + khi));

#pragma unroll
        for (int ks = 0; ks < 4; ks++) {
            const int cur = ks & 1, nxt = cur ^ 1;
            const int kc16n = ((ks + 1) * 2) * 16 + khi;   // next chunk k offset
            // B prefetch for ks+1, then interleave A prefetches among MMA groups
            if (ks < 3) LOADB_T(bfr[nxt], bT, ks + 1);
#pragma unroll
            for (int ni = 0; ni < 4; ni++)
                MMA16816(acc[0][ni][0], acc[0][ni][1], acc[0][ni][2], acc[0][ni][3],
                         av[cur][0][0], av[cur][0][1], av[cur][0][2], av[cur][0][3],
                         bfr[cur][ni][0], bfr[cur][ni][1]);
            if (ks < 3)
                LDSM4(av[nxt][0][0], av[nxt][0][1], av[nxt][0][2], av[nxt][0][3],
                      aT + SW128(rA * 128 + kc16n));
#pragma unroll
            for (int ni = 0; ni < 4; ni++)
                MMA16816(acc[1][ni][0], acc[1][ni][1], acc[1][ni][2], acc[1][ni][3],
                         av[cur][1][0], av[cur][1][1], av[cur][1][2], av[cur][1][3],
                         bfr[cur][ni][0], bfr[cur][ni][1]);
            if (ks < 3)
                LDSM4(av[nxt][1][0], av[nxt][1][1], av[nxt][1][2], av[nxt][1][3],
                      aT + SW128((rA + 16) * 128 + kc16n));
#pragma unroll
            for (int ni = 0; ni < 4; ni++)
                MMA16816(acc[2][ni][0], acc[2][ni][1], acc[2][ni][2], acc[2][ni][3],
                         av[cur][2][0], av[cur][2][1], av[cur][2][2], av[cur][2][3],
                         bfr[cur][ni][0], bfr[cur][ni][1]);
            if (ks < 3)
                LDSM4(av[nxt][2][0], av[nxt][2][1], av[nxt][2][2], av[nxt][2][3],
                      aT + SW128((rA + 32) * 128 + kc16n));
#pragma unroll
            for (int ni = 0; ni < 4; ni++)
                MMA16816(acc[3][ni][0], acc[3][ni][1], acc[3][ni][2], acc[3][ni][3],
                         av[cur][3][0], av[cur][3][1], av[cur][3][2], av[cur][3][3],
                         bfr[cur][ni][0], bfr[cur][ni][1]);
            if (ks < 3)
                LDSM4(av[nxt][3][0], av[nxt][3][1], av[nxt][3][2], av[nxt][3][3],
                      aT + SW128((rA + 48) * 128 + kc16n));
        }
    }

#pragma unroll
    for (int mi = 0; mi < 4; mi++)
#pragma unroll
        for (int ni = 0; ni < 4; ni++) {
            int r = mi * 16 + g;
            int col = wn * 32 + ni * 8 + tg * 2;
            *(float2*)&Cb[(size_t)r * 128 + col] =
                make_float2(acc[mi][ni][0], acc[mi][ni][1]);
            *(float2*)&Cb[(size_t)(r + 8) * 128 + col] =
                make_float2(acc[mi][ni][2], acc[mi][ni][3]);
        }
}

// ---------------- per-mode channel mixing (single-sync, fp16 W) ---------------
__global__ void __launch_bounds__(256) kMix() {
    __shared__ float xs[32][128];
    __shared__ __half ws[128][64];
    int m = blockIdx.x, hh = blockIdx.y;
    int t = threadIdx.x;
#pragma unroll
    for (int i = 0; i < 4; i++) {
        int idx = i * 256 + t;
        int bb = idx >> 5;
        int cc = (idx & 31) << 2;
        *(float4*)&xs[bb][cc] =
            *(const float4*)&g_xspec[((size_t)bb * M_ + m) * CI_ + cc];
    }
    const __half* Wm = g_Wt16 + (size_t)m * CI_ * CO_ + hh * 64;
#pragma unroll
    for (int i = 0; i < 8; i++) {
        int idx = i * 256 + t;
        int cr = idx >> 4, oc = (idx & 15) << 2;
        *(uint2*)&ws[cr][oc] = *(const uint2*)&Wm[(size_t)cr * CO_ + oc];
    }
    __syncthreads();

    int tx = t & 15, ty = t >> 4;
    unsigned long long acc[2][2];
    acc[0][0] = acc[0][1] = acc[1][0] = acc[1][1] = 0ull;
#pragma unroll 16
    for (int k = 0; k < CI_; k++) {
        __half2 h01 = *(const __half2*)&ws[k][tx << 2];
        __half2 h23 = *(const __half2*)&ws[k][(tx << 2) + 2];
        float2 f01 = __half22float2(h01);
        float2 f23 = __half22float2(h23);
        unsigned long long b01 = pk2(f01.x, f01.y);
        unsigned long long b23 = pk2(f23.x, f23.y);
#pragma unroll
        for (int i = 0; i < 2; i++) {
            float a = xs[ty * 2 + i][k];
            unsigned long long ad = pk2(a, a);
            acc[i][0] = ffma2(ad, b01, acc[i][0]);
            acc[i][1] = ffma2(ad, b23, acc[i][1]);
        }
    }
#pragma unroll
    for (int i = 0; i < 2; i++) {
        float4 v;
        upk2(acc[i][0], v.x, v.y);
        upk2(acc[i][1], v.z, v.w);
        int bb = ty * 2 + i;
        union { __half2 h[2]; uint2 u; } cv;
        cv.h[0] = __floats2half2_rn(v.x, v.y);
        cv.h[1] = __floats2half2_rn(v.z, v.w);
        *(uint2*)(g_oM16 + ((size_t)bb * M_ + m) * CO_ + hh * 64 + (tx << 2)) = cv.u;
    }
}

// ---------------- launch ----------------
extern "C" void kernel_launch(void* const* d_in, const int* in_sizes, int n_in,
                              void* d_out, int out_size) {
    const float* x = (const float*)d_in[0];   // [B, N, C_in]
    const float* U = (const float*)d_in[1];   // [N, M]
    const float* W = (const float*)d_in[2];   // [C_in, C_out, M]
    float* out = (float*)d_out;               // [B, N, C_out]

    float* pXs;
    __half *pU, *pO;
    cudaGetSymbolAddress((void**)&pXs, g_xspec);
    cudaGetSymbolAddress((void**)&pU, g_U16);
    cudaGetSymbolAddress((void**)&pO, g_oM16);

    cudaFuncSetAttribute(kGemm1F, cudaFuncAttributeMaxDynamicSharedMemorySize, SM_TOTAL);
    cudaFuncSetAttribute(kGemm2, cudaFuncAttributeMaxDynamicSharedMemorySize, G2_SM);

    // prep: U cast + W transpose/cast + zero g_xspec
    kPrep<<<PREP_TOTAL, 256>>>(U, W);

    // GEMM1 (fused x cast, REDG accumulate)
    kGemm1F<<<dim3(M_ / 128, B_, KSPLIT), 256, SM_TOTAL>>>(pU, x, pXs);

    // mixing
    kMix<<<dim3(M_, 2), 256>>>();

    // GEMM2: 64-row tiles, 4 CTAs/SM, full fragment double-buffering
    kGemm2<<<dim3(N_ / 64, B_), 128, G2_SM>>>(pU, pO, out);
}